// round 11
// baseline (speedup 1.0000x reference)
#include <cuda_runtime.h>
#include <stdint.h>
#include <math.h>

// Problem constants
#define B_TOTAL 8192
#define T_STEPS 60
#define F_IN    158
#define HDIM    32
#define G4      128
#define NBLK    128                    // 64-row tiles in g_xg layout
#define KP      79                     // k-pairs covering F_IN
#define TPAIRS  30

typedef unsigned long long u64;
typedef ulonglong2 u64x2;

// 251.7 MB scratch: xg[tile][m(64)][n(128)], tile = t*NBLK + blk
__device__ __align__(256) float g_xg[(size_t)T_STEPS * NBLK * 64 * G4];

// ---------------- helpers ----------------
__device__ __forceinline__ void ffma2(u64 &acc, u64 a, u64 b) {
    asm("fma.rn.f32x2 %0, %1, %2, %0;" : "+l"(acc) : "l"(a), "l"(b));
}
__device__ __forceinline__ u64 pack2(float x, float y) {
    u64 r; asm("mov.b64 %0, {%1, %2};" : "=l"(r) : "f"(x), "f"(y)); return r;
}
__device__ __forceinline__ float2 unpack2(u64 v) {
    float2 r; asm("mov.b64 {%0, %1}, %2;" : "=f"(r.x), "=f"(r.y) : "l"(v)); return r;
}
__device__ __forceinline__ float tanha(float x) {
    float y; asm("tanh.approx.f32 %0, %1;" : "=f"(y) : "f"(x)); return y;
}
__device__ __forceinline__ float sigf(float x) {      // 0.5*tanh(x/2)+0.5
    return fmaf(0.5f, tanha(0.5f * x), 0.5f);
}
__device__ __forceinline__ void cp_async16(uint32_t dst, const void* src) {
    asm volatile("cp.async.cg.shared.global [%0], [%1], 16;" :: "r"(dst), "l"(src));
}
__device__ __forceinline__ void cp_commit() { asm volatile("cp.async.commit_group;"); }
__device__ __forceinline__ void cp_wait1()  { asm volatile("cp.async.wait_group 1;" ::: "memory"); }

// =======================================================================
// Kernel A: xg = x @ W_ih0^T, timestep-pair items, 512 threads.
//   TRIPLE-buffered x -> ONE __syncthreads per item.
//   Weight layout: sWp[kp*128 + n] = (W[n][2kp], W[n][2kp+1]) u64,
//   lane-contiguous -> conflict-free LDS.64.
// =======================================================================
#define A_THREADS 512
#define A_ROWS    32
#define A_XROW    320
#define A_XBUF    (A_ROWS * A_XROW)        // 10240 floats per buffer
#define A_ITEMS   (TPAIRS * 256)           // 7680
#define A_SW_U64  (KP * G4)                // 10112 u64 = 80896 B
#define A_SMEM_BYTES (A_SW_U64 * 8 + 3 * A_XBUF * 4)   // 203776 B

__device__ __forceinline__ void a_copy_item(const float* __restrict__ x,
                                            int item, float* xbuf, int tid) {
    int tp = item >> 8;
    int rem = item & 255;
    int blk = rem >> 1, half = rem & 1;
    const char* sb = (const char*)x
        + (size_t)(blk * 64 + half * 32) * (F_IN * T_STEPS * 4)
        + (size_t)tp * 1264;                       // 2*158*4 bytes, 16B aligned
    uint32_t db = (uint32_t)__cvta_generic_to_shared(xbuf);
    for (int i = tid; i < A_ROWS * KP; i += A_THREADS) {
        int r = i / KP, c = i - r * KP;            // 79 x 16B chunks = 316 floats
        cp_async16(db + r * (A_XROW * 4) + 16 * c,
                   sb + (size_t)r * (F_IN * T_STEPS * 4) + 16 * c);
    }
}

__global__ void __launch_bounds__(A_THREADS)
xg_kernel(const float* __restrict__ x, const float* __restrict__ Wih0) {
    extern __shared__ char smraw[];
    u64*   sWp = (u64*)smraw;                      // [kp][n] = (W[n][2kp],W[n][2kp+1])
    float* xb  = (float*)(smraw + A_SW_U64 * 8);   // [3][32][320]

    const int tid = threadIdx.x;
    const int lane = tid & 31, wrp = tid >> 5;
    const int r0 = wrp * 2;                        // 16 warps x 2 rows

    for (int i = tid; i < KP * G4; i += A_THREADS) {
        int kp = i >> 7, n = i & 127;
        sWp[kp * G4 + n] = *(const u64*)(Wih0 + n * F_IN + 2 * kp);
    }

    // prologue: prefetch items i0, i1 into buffers 0, 1
    {
        int i0 = blockIdx.x;
        if (i0 < A_ITEMS) a_copy_item(x, i0, xb, tid);
        cp_commit();
        int i1 = i0 + gridDim.x;
        if (i1 < A_ITEMS) a_copy_item(x, i1, xb + A_XBUF, tid);
        cp_commit();
    }

    int cnt = 0;
    for (int item = blockIdx.x; item < A_ITEMS; item += gridDim.x, ++cnt) {
        cp_wait1();               // copies for THIS item complete (mine)
        __syncthreads();          // ... and everyone else's; weights resident

        int bufc = cnt - (cnt / 3) * 3;
        const float* xbase = xb + bufc * A_XBUF + r0 * A_XROW;

        u64 acc[2][4][2];          // [tile][g][row], k-parity split in the u64
#pragma unroll
        for (int ti = 0; ti < 2; ++ti)
#pragma unroll
            for (int g = 0; g < 4; ++g) { acc[ti][g][0] = 0ULL; acc[ti][g][1] = 0ULL; }

#pragma unroll 1
        for (int kp2 = 0; kp2 < 39; ++kp2) {       // kp = 2*kp2, 2*kp2+1
            const float* xk = xbase + 4 * kp2;
            u64 x0a[2], x0b[2], x1a[2], x1b[2];
#pragma unroll
            for (int q = 0; q < 2; ++q) {
                u64x2 v = *(const u64x2*)(xk + q * A_XROW);        // tile0 kp,kp+1
                x0a[q] = v.x; x0b[q] = v.y;
                x1a[q] = *(const u64*)(xk + q * A_XROW + 158);     // tile1 kp
                x1b[q] = *(const u64*)(xk + q * A_XROW + 160);     // tile1 kp+1
            }
            const u64* wp0 = sWp + (2 * kp2) * G4 + lane;
            const u64* wp1 = wp0 + G4;
#pragma unroll
            for (int g = 0; g < 4; ++g) {
                u64 wa = wp0[32 * g];              // kp,   gate g
                u64 wc = wp1[32 * g];              // kp+1, gate g
#pragma unroll
                for (int q = 0; q < 2; ++q) {
                    ffma2(acc[0][g][q], x0a[q], wa);
                    ffma2(acc[0][g][q], x0b[q], wc);
                    ffma2(acc[1][g][q], x1a[q], wa);
                    ffma2(acc[1][g][q], x1b[q], wc);
                }
            }
        }
        {   // tail kp = 78
            const float* xk = xbase + 156;
            const u64* wp = sWp + 78 * G4 + lane;
#pragma unroll
            for (int q = 0; q < 2; ++q) {
                u64 x0 = *(const u64*)(xk + q * A_XROW);
                u64 x1 = *(const u64*)(xk + q * A_XROW + 158);
#pragma unroll
                for (int g = 0; g < 4; ++g) {
                    u64 wa = wp[32 * g];
                    ffma2(acc[0][g][q], x0, wa);
                    ffma2(acc[1][g][q], x1, wa);
                }
            }
        }

        // fold k-parity halves, direct coalesced STG.32
        {
            int tp = item >> 8;
            int rem = item & 255;
            int blk = rem >> 1, half = rem & 1;
#pragma unroll
            for (int ti = 0; ti < 2; ++ti) {
                int t = 2 * tp + ti;
                float* dst = g_xg + ((size_t)t * NBLK + blk) * (64 * G4)
                                  + (size_t)(half * 32 + r0) * G4 + lane;
#pragma unroll
                for (int q = 0; q < 2; ++q)
#pragma unroll
                    for (int g = 0; g < 4; ++g) {
                        float2 v = unpack2(acc[ti][g][q]);
                        dst[q * G4 + 32 * g] = v.x + v.y;
                    }
            }
        }

        // prefetch item+2 into buffer (cnt+2)%3 — safe: all threads passed
        // sync(cnt), i.e. finished compute(cnt-1); this buffer was last read
        // at compute(cnt-1).
        int nxt2 = item + 2 * gridDim.x;
        int bufn = bufc + 2; if (bufn >= 3) bufn -= 3;
        if (nxt2 < A_ITEMS) a_copy_item(x, nxt2, xb + bufn * A_XBUF, tid);
        cp_commit();               // unconditional: keeps group counting uniform
    }
}

// =======================================================================
// Kernel B: recurrence. 256 CTAs x 256 threads, 32 rows/CTA, 4 rows/warp
// (2 CTAs/SM -> 4 warps/SMSP). Dup'd f32x2 weights in [k][n] u64 layout
// (lane-contiguous LDS.64); h via broadcast LDS.128; warp-private h state,
// no block barriers in the loop.
// =======================================================================
#define B_THREADS 256
#define B_CTAS    256                          // 32 rows each
#define HP2       36                           // h row pad (floats)
#define B_SWU     (HDIM * G4)                  // 4096 u64 per matrix
#define B_SMEM_BYTES (3 * B_SWU * 8 + 2 * HDIM * HP2 * 4)   // 107520 B

__global__ void __launch_bounds__(B_THREADS)
lstm_rec_kernel(const float* __restrict__ Whh0, const float* __restrict__ Wih1,
                const float* __restrict__ Whh1, const float* __restrict__ W1,
                const float* __restrict__ b1,   const float* __restrict__ W2,
                float* __restrict__ out) {
    extern __shared__ char smraw[];
    u64* sW0 = (u64*)smraw;                        // Whh0 dup'd [k][128]
    u64* sW1 = sW0 + B_SWU;                        // Wih1
    u64* sW2 = sW1 + B_SWU;                        // Whh1
    float* h1 = (float*)(sW2 + B_SWU);             // [32][36]
    float* h2 = h1 + HDIM * HP2;

    const int tid = threadIdx.x;
    const int j = tid & 31, wrp = tid >> 5;
    const int m0 = wrp * 4;                        // 8 warps x 4 rows = 32
    const int blk = blockIdx.x;

    for (int i = tid; i < HDIM * G4; i += B_THREADS) {
        int k = i >> 7, n = i & 127;
        float w0 = Whh0[n * HDIM + k];
        float w1 = Wih1[n * HDIM + k];
        float w2 = Whh1[n * HDIM + k];
        sW0[i] = pack2(w0, w0);
        sW1[i] = pack2(w1, w1);
        sW2[i] = pack2(w2, w2);
    }
    for (int i = tid; i < 2 * HDIM * HP2; i += B_THREADS) h1[i] = 0.0f;
    __syncthreads();

    float c1[4] = {0.f, 0.f, 0.f, 0.f};
    float c2[4] = {0.f, 0.f, 0.f, 0.f};

    for (int t = 0; t < T_STEPS; ++t) {
        // coalesced xg prefetch for this CTA's 32 rows (consumed after gemm)
        const float* xt = g_xg + ((size_t)t * NBLK + (blk >> 1)) * (64 * G4)
                               + (size_t)((blk & 1) * 32) * G4;
        float xr[4][4];                            // [g][row]
#pragma unroll
        for (int g = 0; g < 4; ++g)
#pragma unroll
            for (int q = 0; q < 4; ++q)
                xr[g][q] = __ldg(xt + (m0 + q) * G4 + j + 32 * g);

        // ---- layer 1: acc = h1 @ Whh0^T ----
        u64 acc[4][2];                             // [g][rowpair]
#pragma unroll
        for (int g = 0; g < 4; ++g) { acc[g][0] = 0ULL; acc[g][1] = 0ULL; }

#pragma unroll 8
        for (int k = 0; k < HDIM; ++k) {
            u64x2 ha = *(const u64x2*)(h1 + k * HP2 + m0);       // rows m0..m0+3
            const u64* wk = sW0 + k * G4 + j;
#pragma unroll
            for (int g = 0; g < 4; ++g) {
                u64 wv = wk[32 * g];
                ffma2(acc[g][0], ha.x, wv);
                ffma2(acc[g][1], ha.y, wv);
            }
        }

        float hn[4];
#pragma unroll
        for (int p = 0; p < 2; ++p) {
            float2 iv = unpack2(acc[0][p]);
            float2 fv = unpack2(acc[1][p]);
            float2 gv = unpack2(acc[2][p]);
            float2 ov = unpack2(acc[3][p]);
            iv.x += xr[0][2 * p]; iv.y += xr[0][2 * p + 1];
            fv.x += xr[1][2 * p]; fv.y += xr[1][2 * p + 1];
            gv.x += xr[2][2 * p]; gv.y += xr[2][2 * p + 1];
            ov.x += xr[3][2 * p]; ov.y += xr[3][2 * p + 1];
            float ca = sigf(fv.x) * c1[2 * p]     + sigf(iv.x) * tanha(gv.x);
            float cb = sigf(fv.y) * c1[2 * p + 1] + sigf(iv.y) * tanha(gv.y);
            c1[2 * p] = ca; c1[2 * p + 1] = cb;
            hn[2 * p]     = sigf(ov.x) * tanha(ca);
            hn[2 * p + 1] = sigf(ov.y) * tanha(cb);
        }
        __syncwarp();              // all lanes done reading old h1
        *(float4*)(h1 + j * HP2 + m0) = make_float4(hn[0], hn[1], hn[2], hn[3]);
        __syncwarp();              // new h1 visible warp-wide

        // ---- layer 2: acc = h1_new @ Wih1^T + h2 @ Whh1^T ----
#pragma unroll
        for (int g = 0; g < 4; ++g) { acc[g][0] = 0ULL; acc[g][1] = 0ULL; }

#pragma unroll 8
        for (int k = 0; k < HDIM; ++k) {
            u64x2 ha = *(const u64x2*)(h1 + k * HP2 + m0);
            u64x2 ga = *(const u64x2*)(h2 + k * HP2 + m0);
            const u64* wka = sW1 + k * G4 + j;
            const u64* wkb = sW2 + k * G4 + j;
#pragma unroll
            for (int g = 0; g < 4; ++g) {
                u64 wa = wka[32 * g];
                u64 wb = wkb[32 * g];
                ffma2(acc[g][0], ha.x, wa);
                ffma2(acc[g][1], ha.y, wa);
                ffma2(acc[g][0], ga.x, wb);
                ffma2(acc[g][1], ga.y, wb);
            }
        }

#pragma unroll
        for (int p = 0; p < 2; ++p) {
            float2 iv = unpack2(acc[0][p]);
            float2 fv = unpack2(acc[1][p]);
            float2 gv = unpack2(acc[2][p]);
            float2 ov = unpack2(acc[3][p]);
            float ca = sigf(fv.x) * c2[2 * p]     + sigf(iv.x) * tanha(gv.x);
            float cb = sigf(fv.y) * c2[2 * p + 1] + sigf(iv.y) * tanha(gv.y);
            c2[2 * p] = ca; c2[2 * p + 1] = cb;
            hn[2 * p]     = sigf(ov.x) * tanha(ca);
            hn[2 * p + 1] = sigf(ov.y) * tanha(cb);
        }
        __syncwarp();
        *(float4*)(h2 + j * HP2 + m0) = make_float4(hn[0], hn[1], hn[2], hn[3]);
        __syncwarp();
    }
    __syncthreads();

    // ---- epilogue: y = relu(c_n @ W1^T + b1) @ W2^T ----
    float* cs = (float*)smraw;                     // overlay on weight region
#pragma unroll
    for (int q = 0; q < 4; ++q) {
        cs[(m0 + q) * 33 + j]      = c1[q];
        cs[(32 + m0 + q) * 33 + j] = c2[q];
    }
    __syncthreads();

    if (tid < 64) {
        int L = tid >> 5, m = tid & 31;
        const float* crow = &cs[(L * 32 + m) * 33];
        float y = 0.0f;
#pragma unroll
        for (int u = 0; u < 16; ++u) {
            float s = __ldg(&b1[u]);
#pragma unroll
            for (int q = 0; q < 32; ++q) s += crow[q] * __ldg(&W1[u * 32 + q]);
            y += fmaxf(s, 0.0f) * __ldg(&W2[u]);
        }
        out[L * B_TOTAL + blk * 32 + m] = y;
    }
}

extern "C" void kernel_launch(void* const* d_in, const int* in_sizes, int n_in,
                              void* d_out, int out_size) {
    const float* x    = (const float*)d_in[0];
    const float* Wih0 = (const float*)d_in[1];
    const float* Whh0 = (const float*)d_in[2];
    const float* Wih1 = (const float*)d_in[3];
    const float* Whh1 = (const float*)d_in[4];
    const float* W1   = (const float*)d_in[5];
    const float* b1   = (const float*)d_in[6];
    const float* W2   = (const float*)d_in[7];
    float* out        = (float*)d_out;

    cudaFuncSetAttribute(xg_kernel, cudaFuncAttributeMaxDynamicSharedMemorySize, A_SMEM_BYTES);
    cudaFuncSetAttribute(lstm_rec_kernel, cudaFuncAttributeMaxDynamicSharedMemorySize, B_SMEM_BYTES);

    int dev = 0;
    cudaGetDevice(&dev);
    int sms = 148;
    cudaDeviceGetAttribute(&sms, cudaDevAttrMultiProcessorCount, dev);
    if (sms < 1) sms = 148;
    int agrid = (sms < A_ITEMS) ? sms : A_ITEMS;

    xg_kernel<<<agrid, A_THREADS, A_SMEM_BYTES>>>(x, Wih0);
    lstm_rec_kernel<<<B_CTAS, B_THREADS, B_SMEM_BYTES>>>(Whh0, Wih1, Whh1, W1, b1, W2, out);
}

// round 12
// speedup vs baseline: 1.2454x; 1.2454x over previous
#include <cuda_runtime.h>
#include <cuda_bf16.h>
#include <stdint.h>
#include <math.h>

// Problem constants
#define B_TOTAL 8192
#define T_STEPS 60
#define F_IN    158
#define HDIM    32
#define G4      128
#define NBLK    128                    // 64-row tiles in g_xg layout
#define NITEMS  (T_STEPS * 64)         // (t, 128-row block) items = 3840

typedef unsigned long long u64;
typedef ulonglong2 u64x2;

// 251.7 MB scratch: xg[tile][m(64)][n(128)], tile = t*NBLK + blk
__device__ __align__(256) float g_xg[(size_t)T_STEPS * NBLK * 64 * G4];

// ---------------- helpers ----------------
__device__ __forceinline__ void ffma2(u64 &acc, u64 a, u64 b) {
    asm("fma.rn.f32x2 %0, %1, %2, %0;" : "+l"(acc) : "l"(a), "l"(b));
}
__device__ __forceinline__ u64 pack2s(float x) {
    u64 r; asm("mov.b64 %0, {%1, %1};" : "=l"(r) : "f"(x)); return r;
}
__device__ __forceinline__ float2 unpack2(u64 v) {
    float2 r; asm("mov.b64 {%0, %1}, %2;" : "=f"(r.x), "=f"(r.y) : "l"(v)); return r;
}
__device__ __forceinline__ float tanha(float x) {
    float y; asm("tanh.approx.f32 %0, %1;" : "=f"(y) : "f"(x)); return y;
}
__device__ __forceinline__ float sigf(float x) {      // 0.5*tanh(x/2)+0.5
    return fmaf(0.5f, tanha(0.5f * x), 0.5f);
}

// bf16 hi/lo split of a float2 -> two packed bf16x2 words
__device__ __forceinline__ void split_pair(float2 v, uint32_t &hw, uint32_t &lw) {
    __nv_bfloat16 h0 = __float2bfloat16(v.x);
    __nv_bfloat16 h1 = __float2bfloat16(v.y);
    __nv_bfloat16 l0 = __float2bfloat16(v.x - __bfloat162float(h0));
    __nv_bfloat16 l1 = __float2bfloat16(v.y - __bfloat162float(h1));
    hw = ((uint32_t)__bfloat16_as_ushort(h1) << 16) | __bfloat16_as_ushort(h0);
    lw = ((uint32_t)__bfloat16_as_ushort(l1) << 16) | __bfloat16_as_ushort(l0);
}

// D(m16n8) += A(m16k16 row) * B(k16n8 col), bf16 in, f32 accum
__device__ __forceinline__ void mma_bf16(float d[4],
                                         uint32_t a0, uint32_t a1, uint32_t a2, uint32_t a3,
                                         uint32_t b0, uint32_t b1) {
    asm volatile(
        "mma.sync.aligned.m16n8k16.row.col.f32.bf16.bf16.f32 "
        "{%0,%1,%2,%3}, {%4,%5,%6,%7}, {%8,%9}, {%0,%1,%2,%3};"
        : "+f"(d[0]), "+f"(d[1]), "+f"(d[2]), "+f"(d[3])
        : "r"(a0), "r"(a1), "r"(a2), "r"(a3), "r"(b0), "r"(b1));
}

// =======================================================================
// Kernel A (mma.sync bf16): xg = x @ W_ih0^T
//   item = (t, bb): 128 batch rows, one timestep. 3-term bf16 split.
//   smem planes (row stride 336 B = 168 bf16, conflict-free frag loads):
//     Wh/Wl: [128 n][168 k]   Xh/Xl: [128 m][168 k]
//   16 warps: warp w = (mw = w&7, nw = w>>3) owns m16 x n64.
// =======================================================================
#define A_THREADS 512
#define RSTB      336                        // row stride bytes
#define PLANE_B   (128 * RSTB)               // 43008 B per plane
#define A_WH      0
#define A_WL      (A_WH + PLANE_B)
#define A_XH      (A_WL + PLANE_B)
#define A_XL      (A_XH + PLANE_B)
#define A_SMEM_BYTES (A_XL + PLANE_B)        // 172032 B

__global__ void __launch_bounds__(A_THREADS)
xg_kernel(const float* __restrict__ x, const float* __restrict__ Wih0) {
    extern __shared__ char sm[];
    char* Wh = sm + A_WH;
    char* Wl = sm + A_WL;
    char* Xh = sm + A_XH;
    char* Xl = sm + A_XL;

    const int tid = threadIdx.x;
    const int lane = tid & 31, w = tid >> 5;
    const int mw = w & 7, nw = w >> 3;           // 8 m-tiles x 2 n-halves
    const int g = lane >> 2, tq = lane & 3;

    // ---- weights: fp32 -> bf16 hi/lo planes (once); p==79 zeros k=158,159 ----
    for (int i = tid; i < 128 * 80; i += A_THREADS) {
        int n = i / 80, p = i - n * 80;
        uint32_t hw = 0, lw = 0;
        if (p < 79) {
            float2 v = *(const float2*)(Wih0 + n * F_IN + 2 * p);
            split_pair(v, hw, lw);
        }
        int a = n * RSTB + 4 * p;
        *(uint32_t*)(Wh + a) = hw;
        *(uint32_t*)(Wl + a) = lw;
    }

    const uint32_t aoff = (16 * mw + g) * RSTB + 4 * tq;   // A frag base (this warp)

    for (int item = blockIdx.x; item < NITEMS; item += gridDim.x) {
        const int t = item >> 6, bb = item & 63;
        const int b0 = bb * 128;

        // ---- convert x tile: 128 rows x 79 pairs -> hi/lo planes ----
        for (int i = tid; i < 128 * 80; i += A_THREADS) {
            int r = i / 80, p = i - r * 80;
            uint32_t hw = 0, lw = 0;
            if (p < 79) {
                float2 v = *(const float2*)(x + (size_t)(b0 + r) * (T_STEPS * F_IN)
                                              + t * F_IN + 2 * p);
                split_pair(v, hw, lw);
            }
            int a = r * RSTB + 4 * p;
            *(uint32_t*)(Xh + a) = hw;
            *(uint32_t*)(Xl + a) = lw;
        }
        __syncthreads();                     // planes ready

        float acc[8][4];
#pragma unroll
        for (int nt = 0; nt < 8; ++nt)
#pragma unroll
            for (int q = 0; q < 4; ++q) acc[nt][q] = 0.0f;

#pragma unroll 1
        for (int ks = 0; ks < 10; ++ks) {    // k16 chunks: k = 16*ks
            const int kb = 32 * ks;          // bytes
            uint32_t ah0 = *(const uint32_t*)(Xh + aoff + kb);
            uint32_t ah1 = *(const uint32_t*)(Xh + aoff + kb + 8 * RSTB);
            uint32_t ah2 = *(const uint32_t*)(Xh + aoff + kb + 16);
            uint32_t ah3 = *(const uint32_t*)(Xh + aoff + kb + 8 * RSTB + 16);
            uint32_t al0 = *(const uint32_t*)(Xl + aoff + kb);
            uint32_t al1 = *(const uint32_t*)(Xl + aoff + kb + 8 * RSTB);
            uint32_t al2 = *(const uint32_t*)(Xl + aoff + kb + 16);
            uint32_t al3 = *(const uint32_t*)(Xl + aoff + kb + 8 * RSTB + 16);
#pragma unroll
            for (int nt = 0; nt < 8; ++nt) {
                const uint32_t boff = (uint32_t)(64 * nw + 8 * nt + g) * RSTB + 4 * tq + kb;
                uint32_t bh0 = *(const uint32_t*)(Wh + boff);
                uint32_t bh1 = *(const uint32_t*)(Wh + boff + 16);
                uint32_t bl0 = *(const uint32_t*)(Wl + boff);
                uint32_t bl1 = *(const uint32_t*)(Wl + boff + 16);
                mma_bf16(acc[nt], ah0, ah1, ah2, ah3, bh0, bh1);   // xh*wh
                mma_bf16(acc[nt], ah0, ah1, ah2, ah3, bl0, bl1);   // xh*wl
                mma_bf16(acc[nt], al0, al1, al2, al3, bh0, bh1);   // xl*wh
            }
        }

        // ---- store D frags to g_xg[t][blk][m64][n128] ----
        {
            const int m = 16 * mw + g;
            const int m2 = m + 8;
            float* base0 = g_xg + ((size_t)t * NBLK + 2 * bb + (m >> 6)) * (64 * G4)
                                + (size_t)(m & 63) * G4;
            float* base1 = g_xg + ((size_t)t * NBLK + 2 * bb + (m2 >> 6)) * (64 * G4)
                                + (size_t)(m2 & 63) * G4;
#pragma unroll
            for (int nt = 0; nt < 8; ++nt) {
                const int col = 64 * nw + 8 * nt + 2 * tq;
                *(float2*)(base0 + col) = make_float2(acc[nt][0], acc[nt][1]);
                *(float2*)(base1 + col) = make_float2(acc[nt][2], acc[nt][3]);
            }
        }
        __syncthreads();                     // all reads done before next convert
    }
}

// =======================================================================
// Kernel B: recurrence — EXACT R6 version (measured 298.5 us).
// 128 CTAs x 256 thr, 8 rows/warp, non-dup LDS.32 weights + pack movs,
// broadcast LDS.128 h, tanh.approx activations, no block barriers in loop.
// =======================================================================
#define B_THREADS 256
#define HPAD 68
#define B_SW  (HDIM * G4)                      // 4096 floats per matrix
#define B_SMEM_BYTES (3 * B_SW * 4 + 2 * HDIM * HPAD * 4)   // 66560 B

__global__ void __launch_bounds__(B_THREADS)
lstm_rec_kernel(const float* __restrict__ Whh0, const float* __restrict__ Wih1,
                const float* __restrict__ Whh1, const float* __restrict__ W1,
                const float* __restrict__ b1,   const float* __restrict__ W2,
                float* __restrict__ out) {
    extern __shared__ char smraw[];
    float* sW0 = (float*)smraw;                     // Whh0 [k][128]
    float* sW1 = sW0 + B_SW;                        // Wih1
    float* sW2 = sW1 + B_SW;                        // Whh1
    float* h1  = sW2 + B_SW;                        // [32][68]
    float* h2  = h1 + HDIM * HPAD;

    const int tid = threadIdx.x;
    const int j = tid & 31, wrp = tid >> 5;
    const int m0 = wrp * 8;                         // 8 warps x 8 rows
    const int blk = blockIdx.x;

    for (int i = tid; i < HDIM * G4; i += B_THREADS) {
        int k = i >> 7, n = i & 127;
        sW0[i] = Whh0[n * HDIM + k];
        sW1[i] = Wih1[n * HDIM + k];
        sW2[i] = Whh1[n * HDIM + k];
    }
    for (int i = tid; i < 2 * HDIM * HPAD; i += B_THREADS) h1[i] = 0.0f;
    __syncthreads();

    float c1[8], c2[8];
#pragma unroll
    for (int q = 0; q < 8; ++q) { c1[q] = 0.0f; c2[q] = 0.0f; }

    for (int t = 0; t < T_STEPS; ++t) {
        const float* xt = g_xg + ((size_t)t * NBLK + blk) * (64 * G4);
        float xr[4][8];                             // [g][row]
#pragma unroll
        for (int g = 0; g < 4; ++g)
#pragma unroll
            for (int q = 0; q < 8; ++q)
                xr[g][q] = __ldg(xt + (m0 + q) * G4 + j + 32 * g);

        // ---- layer 1: acc = h1 @ Whh0^T ----
        u64 acc[4][4];
#pragma unroll
        for (int g = 0; g < 4; ++g)
#pragma unroll
            for (int p = 0; p < 4; ++p) acc[g][p] = 0ULL;

#pragma unroll 4
        for (int k = 0; k < HDIM; ++k) {
            u64x2 ha = *(const u64x2*)(h1 + k * HPAD + m0);
            u64x2 hb = *(const u64x2*)(h1 + k * HPAD + m0 + 4);
            const float* wk = sW0 + k * G4 + j;
#pragma unroll
            for (int g = 0; g < 4; ++g) {
                u64 wv = pack2s(wk[32 * g]);
                ffma2(acc[g][0], ha.x, wv);
                ffma2(acc[g][1], ha.y, wv);
                ffma2(acc[g][2], hb.x, wv);
                ffma2(acc[g][3], hb.y, wv);
            }
        }

        float hn[8];
#pragma unroll
        for (int p = 0; p < 4; ++p) {
            float2 iv = unpack2(acc[0][p]);
            float2 fv = unpack2(acc[1][p]);
            float2 gv = unpack2(acc[2][p]);
            float2 ov = unpack2(acc[3][p]);
            iv.x += xr[0][2 * p]; iv.y += xr[0][2 * p + 1];
            fv.x += xr[1][2 * p]; fv.y += xr[1][2 * p + 1];
            gv.x += xr[2][2 * p]; gv.y += xr[2][2 * p + 1];
            ov.x += xr[3][2 * p]; ov.y += xr[3][2 * p + 1];
            float ca = sigf(fv.x) * c1[2 * p]     + sigf(iv.x) * tanha(gv.x);
            float cb = sigf(fv.y) * c1[2 * p + 1] + sigf(iv.y) * tanha(gv.y);
            c1[2 * p] = ca; c1[2 * p + 1] = cb;
            hn[2 * p]     = sigf(ov.x) * tanha(ca);
            hn[2 * p + 1] = sigf(ov.y) * tanha(cb);
        }
        __syncwarp();
        *(float4*)(h1 + j * HPAD + m0)     = make_float4(hn[0], hn[1], hn[2], hn[3]);
        *(float4*)(h1 + j * HPAD + m0 + 4) = make_float4(hn[4], hn[5], hn[6], hn[7]);
        __syncwarp();

        // ---- layer 2: acc = h1_new @ Wih1^T + h2 @ Whh1^T ----
#pragma unroll
        for (int g = 0; g < 4; ++g)
#pragma unroll
            for (int p = 0; p < 4; ++p) acc[g][p] = 0ULL;

#pragma unroll 4
        for (int k = 0; k < HDIM; ++k) {
            u64x2 ha = *(const u64x2*)(h1 + k * HPAD + m0);
            u64x2 hb = *(const u64x2*)(h1 + k * HPAD + m0 + 4);
            u64x2 ga = *(const u64x2*)(h2 + k * HPAD + m0);
            u64x2 gb = *(const u64x2*)(h2 + k * HPAD + m0 + 4);
            const float* wka = sW1 + k * G4 + j;
            const float* wkb = sW2 + k * G4 + j;
#pragma unroll
            for (int g = 0; g < 4; ++g) {
                u64 wa = pack2s(wka[32 * g]);
                u64 wb = pack2s(wkb[32 * g]);
                ffma2(acc[g][0], ha.x, wa);
                ffma2(acc[g][1], ha.y, wa);
                ffma2(acc[g][2], hb.x, wa);
                ffma2(acc[g][3], hb.y, wa);
                ffma2(acc[g][0], ga.x, wb);
                ffma2(acc[g][1], ga.y, wb);
                ffma2(acc[g][2], gb.x, wb);
                ffma2(acc[g][3], gb.y, wb);
            }
        }

#pragma unroll
        for (int p = 0; p < 4; ++p) {
            float2 iv = unpack2(acc[0][p]);
            float2 fv = unpack2(acc[1][p]);
            float2 gv = unpack2(acc[2][p]);
            float2 ov = unpack2(acc[3][p]);
            float ca = sigf(fv.x) * c2[2 * p]     + sigf(iv.x) * tanha(gv.x);
            float cb = sigf(fv.y) * c2[2 * p + 1] + sigf(iv.y) * tanha(gv.y);
            c2[2 * p] = ca; c2[2 * p + 1] = cb;
            hn[2 * p]     = sigf(ov.x) * tanha(ca);
            hn[2 * p + 1] = sigf(ov.y) * tanha(cb);
        }
        __syncwarp();
        *(float4*)(h2 + j * HPAD + m0)     = make_float4(hn[0], hn[1], hn[2], hn[3]);
        *(float4*)(h2 + j * HPAD + m0 + 4) = make_float4(hn[4], hn[5], hn[6], hn[7]);
        __syncwarp();
    }
    __syncthreads();

    // ---- epilogue: y = relu(c_n @ W1^T + b1) @ W2^T ----
    float* cs = (float*)smraw;
#pragma unroll
    for (int q = 0; q < 8; ++q) {
        cs[(m0 + q) * 33 + j]      = c1[q];
        cs[(64 + m0 + q) * 33 + j] = c2[q];
    }
    __syncthreads();

    if (tid < 128) {
        int L = tid >> 6, m = tid & 63;
        const float* crow = &cs[(L * 64 + m) * 33];
        float y = 0.0f;
#pragma unroll
        for (int u = 0; u < 16; ++u) {
            float s = __ldg(&b1[u]);
#pragma unroll
            for (int q = 0; q < 32; ++q) s += crow[q] * __ldg(&W1[u * 32 + q]);
            y += fmaxf(s, 0.0f) * __ldg(&W2[u]);
        }
        out[L * B_TOTAL + blk * 64 + m] = y;
    }
}

extern "C" void kernel_launch(void* const* d_in, const int* in_sizes, int n_in,
                              void* d_out, int out_size) {
    const float* x    = (const float*)d_in[0];
    const float* Wih0 = (const float*)d_in[1];
    const float* Whh0 = (const float*)d_in[2];
    const float* Wih1 = (const float*)d_in[3];
    const float* Whh1 = (const float*)d_in[4];
    const float* W1   = (const float*)d_in[5];
    const float* b1   = (const float*)d_in[6];
    const float* W2   = (const float*)d_in[7];
    float* out        = (float*)d_out;

    cudaFuncSetAttribute(xg_kernel, cudaFuncAttributeMaxDynamicSharedMemorySize, A_SMEM_BYTES);
    cudaFuncSetAttribute(lstm_rec_kernel, cudaFuncAttributeMaxDynamicSharedMemorySize, B_SMEM_BYTES);

    int dev = 0;
    cudaGetDevice(&dev);
    int sms = 148;
    cudaDeviceGetAttribute(&sms, cudaDevAttrMultiProcessorCount, dev);
    if (sms < 1) sms = 148;
    int agrid = (sms < NITEMS) ? sms : NITEMS;

    xg_kernel<<<agrid, A_THREADS, A_SMEM_BYTES>>>(x, Wih0);
    lstm_rec_kernel<<<NBLK, B_THREADS, B_SMEM_BYTES>>>(Whh0, Wih1, Whh1, W1, b1, W2, out);
}

// round 13
// speedup vs baseline: 1.8107x; 1.4540x over previous
#include <cuda_runtime.h>
#include <cuda_bf16.h>
#include <stdint.h>
#include <math.h>

// Problem constants
#define B_TOTAL 8192
#define T_STEPS 60
#define F_IN    158
#define HDIM    32
#define G4      128
#define NBLK    128                    // 64-row tiles in g_xg layout
#define NITEMS  (T_STEPS * 128)        // (t, 64-row block) items = 7680

typedef unsigned long long u64;
typedef ulonglong2 u64x2;

// 251.7 MB scratch: xg[tile][m(64)][n(128)], tile = t*NBLK + blk
__device__ __align__(256) float g_xg[(size_t)T_STEPS * NBLK * 64 * G4];

// ---------------- helpers ----------------
__device__ __forceinline__ void ffma2(u64 &acc, u64 a, u64 b) {
    asm("fma.rn.f32x2 %0, %1, %2, %0;" : "+l"(acc) : "l"(a), "l"(b));
}
__device__ __forceinline__ u64 pack2s(float x) {
    u64 r; asm("mov.b64 %0, {%1, %1};" : "=l"(r) : "f"(x)); return r;
}
__device__ __forceinline__ float2 unpack2(u64 v) {
    float2 r; asm("mov.b64 {%0, %1}, %2;" : "=f"(r.x), "=f"(r.y) : "l"(v)); return r;
}
__device__ __forceinline__ float tanha(float x) {
    float y; asm("tanh.approx.f32 %0, %1;" : "=f"(y) : "f"(x)); return y;
}
__device__ __forceinline__ float sigf(float x) {      // 0.5*tanh(x/2)+0.5
    return fmaf(0.5f, tanha(0.5f * x), 0.5f);
}

// bf16 hi/lo split of a float2 -> two packed bf16x2 words
__device__ __forceinline__ void split_pair(float2 v, uint32_t &hw, uint32_t &lw) {
    __nv_bfloat16 h0 = __float2bfloat16(v.x);
    __nv_bfloat16 h1 = __float2bfloat16(v.y);
    __nv_bfloat16 l0 = __float2bfloat16(v.x - __bfloat162float(h0));
    __nv_bfloat16 l1 = __float2bfloat16(v.y - __bfloat162float(h1));
    hw = ((uint32_t)__bfloat16_as_ushort(h1) << 16) | __bfloat16_as_ushort(h0);
    lw = ((uint32_t)__bfloat16_as_ushort(l1) << 16) | __bfloat16_as_ushort(l0);
}

// D(m16n8) += A(m16k16 row) * B(k16n8 col), bf16 in, f32 accum
__device__ __forceinline__ void mma_bf16(float d[4],
                                         uint32_t a0, uint32_t a1, uint32_t a2, uint32_t a3,
                                         uint32_t b0, uint32_t b1) {
    asm volatile(
        "mma.sync.aligned.m16n8k16.row.col.f32.bf16.bf16.f32 "
        "{%0,%1,%2,%3}, {%4,%5,%6,%7}, {%8,%9}, {%0,%1,%2,%3};"
        : "+f"(d[0]), "+f"(d[1]), "+f"(d[2]), "+f"(d[3])
        : "r"(a0), "r"(a1), "r"(a2), "r"(a3), "r"(b0), "r"(b1));
}

// =======================================================================
// Kernel A (mma.sync bf16, pipelined): xg = x @ W_ih0^T
//   item = (t, hb): 64 batch rows (hb*64..), one timestep.
//   Pipeline: LDG x(i+1) -> regs | mma planes[cur] | convert regs -> planes[cur^1]
//   -> ONE __syncthreads per item; gmem latency hidden under mma.
//   Row stride 336 B keeps all A/B frag LDS conflict-free.
//   16 warps: warp w = (mw = w&3, nw = w>>2) owns m16 x n32.
// =======================================================================
#define A_THREADS 512
#define RSTB      336                        // row stride bytes
#define WPLANE_B  (128 * RSTB)               // 43008 B
#define XPLANE_B  (64 * RSTB)                // 21504 B
#define A_WH      0
#define A_WL      (A_WH + WPLANE_B)
#define A_X0H     (A_WL + WPLANE_B)          // buffer 0: hi, lo
#define A_X0L     (A_X0H + XPLANE_B)
#define A_X1H     (A_X0L + XPLANE_B)         // buffer 1
#define A_X1L     (A_X1H + XPLANE_B)
#define A_SMEM_BYTES (A_X1L + XPLANE_B)      // 172032 B

// load 10 float2 x-pairs for one item into regs (p = (tid&7) + 8k)
__device__ __forceinline__ void load_x_regs(const float* __restrict__ x,
                                            int item, int tid, float2 xr[10]) {
    const int t = item >> 7, hb = item & 127;
    const int r = tid >> 3, pb = tid & 7;           // row 0..63, pair base
    const float* src = x + (size_t)(hb * 64 + r) * (T_STEPS * F_IN) + t * F_IN;
#pragma unroll
    for (int k = 0; k < 10; ++k) {
        int p = pb + 8 * k;
        xr[k] = (p < 79) ? *(const float2*)(src + 2 * p) : make_float2(0.f, 0.f);
    }
}
// convert regs into an X plane pair
__device__ __forceinline__ void convert_x(char* Xh, char* Xl, int tid,
                                          const float2 xr[10]) {
    const int r = tid >> 3, pb = tid & 7;
#pragma unroll
    for (int k = 0; k < 10; ++k) {
        int p = pb + 8 * k;
        uint32_t hw, lw;
        split_pair(xr[k], hw, lw);
        int a = r * RSTB + 4 * p;
        *(uint32_t*)(Xh + a) = hw;
        *(uint32_t*)(Xl + a) = lw;
    }
}

__global__ void __launch_bounds__(A_THREADS)
xg_kernel(const float* __restrict__ x, const float* __restrict__ Wih0) {
    extern __shared__ char sm[];
    char* Wh = sm + A_WH;
    char* Wl = sm + A_WL;

    const int tid = threadIdx.x;
    const int lane = tid & 31, w = tid >> 5;
    const int mw = w & 3, nw = w >> 2;           // 4 m16-tiles x 4 n32-tiles
    const int g = lane >> 2, tq = lane & 3;

    // ---- weights: fp32 -> bf16 hi/lo planes (once); p==79 zeros ----
    for (int i = tid; i < 128 * 80; i += A_THREADS) {
        int n = i / 80, p = i - n * 80;
        uint32_t hw = 0, lw = 0;
        if (p < 79) {
            float2 v = *(const float2*)(Wih0 + n * F_IN + 2 * p);
            split_pair(v, hw, lw);
        }
        int a = n * RSTB + 4 * p;
        *(uint32_t*)(Wh + a) = hw;
        *(uint32_t*)(Wl + a) = lw;
    }

    const uint32_t aoff = (16 * mw + g) * RSTB + 4 * tq;   // A frag base

    // prologue: item0 -> regs -> plane buffer 0
    float2 xr[10];
    int item = blockIdx.x;
    if (item < NITEMS) {
        load_x_regs(x, item, tid, xr);
        convert_x(sm + A_X0H, sm + A_X0L, tid, xr);
    }
    __syncthreads();

    int cur = 0;
    for (; item < NITEMS; item += gridDim.x) {
        // issue loads for the NEXT item (completes under the mma below)
        const int nxt = item + gridDim.x;
        if (nxt < NITEMS) load_x_regs(x, nxt, tid, xr);

        const char* Xh = sm + (cur ? A_X1H : A_X0H);
        const char* Xl = sm + (cur ? A_X1L : A_X0L);

        float acc[4][4];
#pragma unroll
        for (int nt = 0; nt < 4; ++nt)
#pragma unroll
            for (int q = 0; q < 4; ++q) acc[nt][q] = 0.0f;

#pragma unroll 2
        for (int ks = 0; ks < 10; ++ks) {    // k16 chunks
            const int kb = 32 * ks;
            uint32_t ah0 = *(const uint32_t*)(Xh + aoff + kb);
            uint32_t ah1 = *(const uint32_t*)(Xh + aoff + kb + 8 * RSTB);
            uint32_t ah2 = *(const uint32_t*)(Xh + aoff + kb + 16);
            uint32_t ah3 = *(const uint32_t*)(Xh + aoff + kb + 8 * RSTB + 16);
            uint32_t al0 = *(const uint32_t*)(Xl + aoff + kb);
            uint32_t al1 = *(const uint32_t*)(Xl + aoff + kb + 8 * RSTB);
            uint32_t al2 = *(const uint32_t*)(Xl + aoff + kb + 16);
            uint32_t al3 = *(const uint32_t*)(Xl + aoff + kb + 8 * RSTB + 16);
#pragma unroll
            for (int nt = 0; nt < 4; ++nt) {
                const uint32_t boff = (uint32_t)(32 * nw + 8 * nt + g) * RSTB + 4 * tq + kb;
                uint32_t bh0 = *(const uint32_t*)(Wh + boff);
                uint32_t bh1 = *(const uint32_t*)(Wh + boff + 16);
                uint32_t bl0 = *(const uint32_t*)(Wl + boff);
                uint32_t bl1 = *(const uint32_t*)(Wl + boff + 16);
                mma_bf16(acc[nt], ah0, ah1, ah2, ah3, bh0, bh1);   // xh*wh
                mma_bf16(acc[nt], ah0, ah1, ah2, ah3, bl0, bl1);   // xh*wl
                mma_bf16(acc[nt], al0, al1, al2, al3, bh0, bh1);   // xl*wh
            }
        }

        // ---- store D frags: g_xg[t][hb][m64][n128] ----
        {
            const int t = item >> 7, hb = item & 127;
            float* base = g_xg + ((size_t)t * NBLK + hb) * (64 * G4);
            const int m = 16 * mw + g;
#pragma unroll
            for (int nt = 0; nt < 4; ++nt) {
                const int col = 32 * nw + 8 * nt + 2 * tq;
                *(float2*)(base + (size_t)m * G4 + col)
                    = make_float2(acc[nt][0], acc[nt][1]);
                *(float2*)(base + (size_t)(m + 8) * G4 + col)
                    = make_float2(acc[nt][2], acc[nt][3]);
            }
        }

        // convert next item's x (regs already in flight) into the other buffer
        if (nxt < NITEMS)
            convert_x(sm + (cur ? A_X0H : A_X1H), sm + (cur ? A_X0L : A_X1L), tid, xr);
        __syncthreads();           // convert writes + this item's plane reads done
        cur ^= 1;
    }
}

// =======================================================================
// Kernel B: recurrence — EXACT R6 version (measured 298.5 us).
// =======================================================================
#define B_THREADS 256
#define HPAD 68
#define B_SW  (HDIM * G4)                      // 4096 floats per matrix
#define B_SMEM_BYTES (3 * B_SW * 4 + 2 * HDIM * HPAD * 4)   // 66560 B

__global__ void __launch_bounds__(B_THREADS)
lstm_rec_kernel(const float* __restrict__ Whh0, const float* __restrict__ Wih1,
                const float* __restrict__ Whh1, const float* __restrict__ W1,
                const float* __restrict__ b1,   const float* __restrict__ W2,
                float* __restrict__ out) {
    extern __shared__ char smraw[];
    float* sW0 = (float*)smraw;                     // Whh0 [k][128]
    float* sW1 = sW0 + B_SW;                        // Wih1
    float* sW2 = sW1 + B_SW;                        // Whh1
    float* h1  = sW2 + B_SW;                        // [32][68]
    float* h2  = h1 + HDIM * HPAD;

    const int tid = threadIdx.x;
    const int j = tid & 31, wrp = tid >> 5;
    const int m0 = wrp * 8;                         // 8 warps x 8 rows
    const int blk = blockIdx.x;

    for (int i = tid; i < HDIM * G4; i += B_THREADS) {
        int k = i >> 7, n = i & 127;
        sW0[i] = Whh0[n * HDIM + k];
        sW1[i] = Wih1[n * HDIM + k];
        sW2[i] = Whh1[n * HDIM + k];
    }
    for (int i = tid; i < 2 * HDIM * HPAD; i += B_THREADS) h1[i] = 0.0f;
    __syncthreads();

    float c1[8], c2[8];
#pragma unroll
    for (int q = 0; q < 8; ++q) { c1[q] = 0.0f; c2[q] = 0.0f; }

    for (int t = 0; t < T_STEPS; ++t) {
        const float* xt = g_xg + ((size_t)t * NBLK + blk) * (64 * G4);
        float xr[4][8];                             // [g][row]
#pragma unroll
        for (int g = 0; g < 4; ++g)
#pragma unroll
            for (int q = 0; q < 8; ++q)
                xr[g][q] = __ldg(xt + (m0 + q) * G4 + j + 32 * g);

        // ---- layer 1: acc = h1 @ Whh0^T ----
        u64 acc[4][4];
#pragma unroll
        for (int g = 0; g < 4; ++g)
#pragma unroll
            for (int p = 0; p < 4; ++p) acc[g][p] = 0ULL;

#pragma unroll 4
        for (int k = 0; k < HDIM; ++k) {
            u64x2 ha = *(const u64x2*)(h1 + k * HPAD + m0);
            u64x2 hb = *(const u64x2*)(h1 + k * HPAD + m0 + 4);
            const float* wk = sW0 + k * G4 + j;
#pragma unroll
            for (int g = 0; g < 4; ++g) {
                u64 wv = pack2s(wk[32 * g]);
                ffma2(acc[g][0], ha.x, wv);
                ffma2(acc[g][1], ha.y, wv);
                ffma2(acc[g][2], hb.x, wv);
                ffma2(acc[g][3], hb.y, wv);
            }
        }

        float hn[8];
#pragma unroll
        for (int p = 0; p < 4; ++p) {
            float2 iv = unpack2(acc[0][p]);
            float2 fv = unpack2(acc[1][p]);
            float2 gv = unpack2(acc[2][p]);
            float2 ov = unpack2(acc[3][p]);
            iv.x += xr[0][2 * p]; iv.y += xr[0][2 * p + 1];
            fv.x += xr[1][2 * p]; fv.y += xr[1][2 * p + 1];
            gv.x += xr[2][2 * p]; gv.y += xr[2][2 * p + 1];
            ov.x += xr[3][2 * p]; ov.y += xr[3][2 * p + 1];
            float ca = sigf(fv.x) * c1[2 * p]     + sigf(iv.x) * tanha(gv.x);
            float cb = sigf(fv.y) * c1[2 * p + 1] + sigf(iv.y) * tanha(gv.y);
            c1[2 * p] = ca; c1[2 * p + 1] = cb;
            hn[2 * p]     = sigf(ov.x) * tanha(ca);
            hn[2 * p + 1] = sigf(ov.y) * tanha(cb);
        }
        __syncwarp();
        *(float4*)(h1 + j * HPAD + m0)     = make_float4(hn[0], hn[1], hn[2], hn[3]);
        *(float4*)(h1 + j * HPAD + m0 + 4) = make_float4(hn[4], hn[5], hn[6], hn[7]);
        __syncwarp();

        // ---- layer 2: acc = h1_new @ Wih1^T + h2 @ Whh1^T ----
#pragma unroll
        for (int g = 0; g < 4; ++g)
#pragma unroll
            for (int p = 0; p < 4; ++p) acc[g][p] = 0ULL;

#pragma unroll 4
        for (int k = 0; k < HDIM; ++k) {
            u64x2 ha = *(const u64x2*)(h1 + k * HPAD + m0);
            u64x2 hb = *(const u64x2*)(h1 + k * HPAD + m0 + 4);
            u64x2 ga = *(const u64x2*)(h2 + k * HPAD + m0);
            u64x2 gb = *(const u64x2*)(h2 + k * HPAD + m0 + 4);
            const float* wka = sW1 + k * G4 + j;
            const float* wkb = sW2 + k * G4 + j;
#pragma unroll
            for (int g = 0; g < 4; ++g) {
                u64 wa = pack2s(wka[32 * g]);
                u64 wb = pack2s(wkb[32 * g]);
                ffma2(acc[g][0], ha.x, wa);
                ffma2(acc[g][1], ha.y, wa);
                ffma2(acc[g][2], hb.x, wa);
                ffma2(acc[g][3], hb.y, wa);
                ffma2(acc[g][0], ga.x, wb);
                ffma2(acc[g][1], ga.y, wb);
                ffma2(acc[g][2], gb.x, wb);
                ffma2(acc[g][3], gb.y, wb);
            }
        }

#pragma unroll
        for (int p = 0; p < 4; ++p) {
            float2 iv = unpack2(acc[0][p]);
            float2 fv = unpack2(acc[1][p]);
            float2 gv = unpack2(acc[2][p]);
            float2 ov = unpack2(acc[3][p]);
            float ca = sigf(fv.x) * c2[2 * p]     + sigf(iv.x) * tanha(gv.x);
            float cb = sigf(fv.y) * c2[2 * p + 1] + sigf(iv.y) * tanha(gv.y);
            c2[2 * p] = ca; c2[2 * p + 1] = cb;
            hn[2 * p]     = sigf(ov.x) * tanha(ca);
            hn[2 * p + 1] = sigf(ov.y) * tanha(cb);
        }
        __syncwarp();
        *(float4*)(h2 + j * HPAD + m0)     = make_float4(hn[0], hn[1], hn[2], hn[3]);
        *(float4*)(h2 + j * HPAD + m0 + 4) = make_float4(hn[4], hn[5], hn[6], hn[7]);
        __syncwarp();
    }
    __syncthreads();

    // ---- epilogue: y = relu(c_n @ W1^T + b1) @ W2^T ----
    float* cs = (float*)smraw;
#pragma unroll
    for (int q = 0; q < 8; ++q) {
        cs[(m0 + q) * 33 + j]      = c1[q];
        cs[(64 + m0 + q) * 33 + j] = c2[q];
    }
    __syncthreads();

    if (tid < 128) {
        int L = tid >> 6, m = tid & 63;
        const float* crow = &cs[(L * 64 + m) * 33];
        float y = 0.0f;
#pragma unroll
        for (int u = 0; u < 16; ++u) {
            float s = __ldg(&b1[u]);
#pragma unroll
            for (int q = 0; q < 32; ++q) s += crow[q] * __ldg(&W1[u * 32 + q]);
            y += fmaxf(s, 0.0f) * __ldg(&W2[u]);
        }
        out[L * B_TOTAL + blk * 64 + m] = y;
    }
}

extern "C" void kernel_launch(void* const* d_in, const int* in_sizes, int n_in,
                              void* d_out, int out_size) {
    const float* x    = (const float*)d_in[0];
    const float* Wih0 = (const float*)d_in[1];
    const float* Whh0 = (const float*)d_in[2];
    const float* Wih1 = (const float*)d_in[3];
    const float* Whh1 = (const float*)d_in[4];
    const float* W1   = (const float*)d_in[5];
    const float* b1   = (const float*)d_in[6];
    const float* W2   = (const float*)d_in[7];
    float* out        = (float*)d_out;

    cudaFuncSetAttribute(xg_kernel, cudaFuncAttributeMaxDynamicSharedMemorySize, A_SMEM_BYTES);
    cudaFuncSetAttribute(lstm_rec_kernel, cudaFuncAttributeMaxDynamicSharedMemorySize, B_SMEM_BYTES);

    int dev = 0;
    cudaGetDevice(&dev);
    int sms = 148;
    cudaDeviceGetAttribute(&sms, cudaDevAttrMultiProcessorCount, dev);
    if (sms < 1) sms = 148;
    int agrid = (sms < NITEMS) ? sms : NITEMS;

    xg_kernel<<<agrid, A_THREADS, A_SMEM_BYTES>>>(x, Wih0);
    lstm_rec_kernel<<<NBLK, B_THREADS, B_SMEM_BYTES>>>(Whh0, Wih1, Whh1, W1, b1, W2, out);
}